// round 1
// baseline (speedup 1.0000x reference)
#include <cuda_runtime.h>

#define BATCH 64
#define TDIM  2048
#define QDIM  512
#define KDIM  512

// Scratch (no allocations allowed in kernel_launch)
__device__ float g_mids[BATCH * KDIM];
__device__ float g_sums[BATCH];

// ---------------------------------------------------------------------------
// Kernel 1: mids[b,k] = sum_q W[k,q] * query[b,q]   (also zeroes g_sums)
// grid = 64 blocks (8 k-tiles x 8 b-tiles), 512 threads.
// Each thread computes one (k, b) pair: kl = tid/8 (64 k's), bl = tid%8.
// query tile lives in padded smem (conflict-free float4 reads).
// ---------------------------------------------------------------------------
__global__ void mids_kernel(const float* __restrict__ query,
                            const float* __restrict__ W)
{
    const int kt = blockIdx.x & 7;   // k tile: 8 tiles of 64
    const int bt = blockIdx.x >> 3;  // b tile: 8 tiles of 8

    if (blockIdx.x == 0 && threadIdx.x < BATCH) g_sums[threadIdx.x] = 0.0f;

    // padded row stride: 516 floats -> rows phase-shifted by 4 banks
    __shared__ float qs[8][QDIM + 4];
    for (int i = threadIdx.x; i < 8 * QDIM; i += blockDim.x) {
        int bb = i >> 9;          // /512
        int q  = i & (QDIM - 1);  // %512
        qs[bb][q] = query[(size_t)(bt * 8 + bb) * QDIM + q];
    }
    __syncthreads();

    const int kl = threadIdx.x >> 3;  // 0..63
    const int bl = threadIdx.x & 7;   // 0..7
    const int k  = kt * 64 + kl;

    const float4* w4 = reinterpret_cast<const float4*>(W + (size_t)k * QDIM);
    const float4* q4 = reinterpret_cast<const float4*>(qs[bl]);

    float acc = 0.0f;
#pragma unroll 8
    for (int j = 0; j < QDIM / 4; j++) {
        float4 w = w4[j];
        float4 v = q4[j];
        acc += w.x * v.x + w.y * v.y + w.z * v.z + w.w * v.w;
    }
    g_mids[(size_t)(bt * 8 + bl) * KDIM + k] = acc;
}

// ---------------------------------------------------------------------------
// Kernel 2: e[b,t] = exp(tanh(key[b,t,:] . mids[b,:] + bias)); accumulate
// per-batch sums. tanh output in (-1,1) -> exp bounded -> no max pass needed.
// grid = 64*16 = 1024 blocks, 256 threads (8 warps).
// Each block: one batch b, 128 t-rows. Each warp: 16 rows, 2 at a time
// (8 independent float4 LDGs in flight to hide shfl-reduce latency).
// Fully coalesced: lane l reads float4 at element offset 4*(l + 32*j).
// ---------------------------------------------------------------------------
__global__ void __launch_bounds__(256)
scores_kernel(const float* __restrict__ key,
              const float* __restrict__ bias,
              float* __restrict__ out)
{
    const int b     = blockIdx.x >> 4;   // 0..63
    const int chunk = blockIdx.x & 15;   // 0..15 (128 rows each)

    __shared__ float ms[KDIM];
    __shared__ float blockSum;
    if (threadIdx.x == 0) blockSum = 0.0f;
    for (int i = threadIdx.x; i < KDIM; i += blockDim.x)
        ms[i] = g_mids[(size_t)b * KDIM + i];
    __syncthreads();

    const float bv   = bias[0];
    const int warp   = threadIdx.x >> 5;
    const int lane   = threadIdx.x & 31;
    const float4* m4 = reinterpret_cast<const float4*>(ms);

    float wsum = 0.0f;
    const int t0 = chunk * 128 + warp * 16;

#pragma unroll 2
    for (int r = 0; r < 16; r += 2) {
        const int ta = t0 + r;
        const int tb = ta + 1;
        const float4* ka = reinterpret_cast<const float4*>(
            key + ((size_t)b * TDIM + ta) * KDIM);
        const float4* kb = reinterpret_cast<const float4*>(
            key + ((size_t)b * TDIM + tb) * KDIM);

        float acc0 = 0.0f, acc1 = 0.0f;
#pragma unroll
        for (int j = 0; j < 4; j++) {
            const int idx = lane + 32 * j;
            float4 va = ka[idx];
            float4 vb = kb[idx];
            float4 mv = m4[idx];
            acc0 += va.x * mv.x + va.y * mv.y + va.z * mv.z + va.w * mv.w;
            acc1 += vb.x * mv.x + vb.y * mv.y + vb.z * mv.z + vb.w * mv.w;
        }
#pragma unroll
        for (int o = 16; o; o >>= 1) {
            acc0 += __shfl_xor_sync(0xffffffffu, acc0, o);
            acc1 += __shfl_xor_sync(0xffffffffu, acc1, o);
        }
        float e0 = __expf(tanhf(acc0 + bv));
        float e1 = __expf(tanhf(acc1 + bv));
        if (lane == 0) {
            out[(size_t)b * TDIM + ta] = e0;
            out[(size_t)b * TDIM + tb] = e1;
            wsum += e0 + e1;
        }
    }

    if (lane == 0) atomicAdd(&blockSum, wsum);
    __syncthreads();
    if (threadIdx.x == 0) atomicAdd(&g_sums[b], blockSum);
}

// ---------------------------------------------------------------------------
// Kernel 3: normalize in place. 32768 float4s, b = (float4 index) / 512.
// ---------------------------------------------------------------------------
__global__ void norm_kernel(float* __restrict__ out)
{
    const int i = blockIdx.x * blockDim.x + threadIdx.x; // 0..32767
    const int b = i >> 9;  // 512 float4 per batch row (T=2048)
    const float inv = 1.0f / g_sums[b];
    float4* o4 = reinterpret_cast<float4*>(out);
    float4 v = o4[i];
    v.x *= inv; v.y *= inv; v.z *= inv; v.w *= inv;
    o4[i] = v;
}

// ---------------------------------------------------------------------------
// Inputs (metadata order): query [64,512], key [64,2048,512], W [512,512],
// bias [1]. Output: [64,2048] float32.
// ---------------------------------------------------------------------------
extern "C" void kernel_launch(void* const* d_in, const int* in_sizes, int n_in,
                              void* d_out, int out_size)
{
    const float* query = (const float*)d_in[0];
    const float* key   = (const float*)d_in[1];
    const float* W     = (const float*)d_in[2];
    const float* bias  = (const float*)d_in[3];
    float* out = (float*)d_out;

    mids_kernel<<<64, 512>>>(query, W);
    scores_kernel<<<BATCH * 16, 256>>>(key, bias, out);
    norm_kernel<<<(BATCH * TDIM / 4) / 256, 256>>>(out);
}

// round 2
// speedup vs baseline: 1.2878x; 1.2878x over previous
#include <cuda_runtime.h>

#define BATCH 64
#define TDIM  2048
#define QDIM  512
#define KDIM  512

// Scratch (no allocations allowed in kernel_launch)
__device__ float g_mids[BATCH * KDIM];
__device__ float g_sums[BATCH];

// ---------------------------------------------------------------------------
// Kernel 1: mids[b,k] = sum_q W[k,q] * query[b,q]   (also zeroes g_sums)
// grid = 256 blocks: kt = x & 7 (8 tiles of 64 k), bt = x >> 3 (32 tiles of
// 2 batches). 256 threads = 8 warps. Each warp owns 8 k's, processed 2 at a
// time against both batches -> 8 independent LDG.128 in flight per step.
// W rows read warp-coalesced (lane -> consecutive float4). W stays in L2
// after wave 1 (1 MB); total L2 traffic 32 MB.
// ---------------------------------------------------------------------------
__global__ void __launch_bounds__(256)
mids_kernel(const float* __restrict__ query,
            const float* __restrict__ W)
{
    const int kt = blockIdx.x & 7;   // 0..7   (64 k each)
    const int bt = blockIdx.x >> 3;  // 0..31  (2 b each)

    if (blockIdx.x == 0 && threadIdx.x < BATCH) g_sums[threadIdx.x] = 0.0f;

    __shared__ float qs[2][QDIM];
    for (int i = threadIdx.x; i < 2 * QDIM; i += blockDim.x) {
        int bb = i >> 9;
        int q  = i & (QDIM - 1);
        qs[bb][q] = query[(size_t)(bt * 2 + bb) * QDIM + q];
    }
    __syncthreads();

    const int warp = threadIdx.x >> 5;
    const int lane = threadIdx.x & 31;
    const float4* q0 = reinterpret_cast<const float4*>(qs[0]);
    const float4* q1 = reinterpret_cast<const float4*>(qs[1]);

#pragma unroll
    for (int kk = 0; kk < 4; kk++) {
        const int k0 = kt * 64 + warp * 8 + kk * 2;
        const int k1 = k0 + 1;
        const float4* w0 = reinterpret_cast<const float4*>(W + (size_t)k0 * QDIM);
        const float4* w1 = reinterpret_cast<const float4*>(W + (size_t)k1 * QDIM);

        float a00 = 0.f, a01 = 0.f, a10 = 0.f, a11 = 0.f;
#pragma unroll
        for (int j = 0; j < 4; j++) {
            const int idx = lane + 32 * j;
            float4 wa = w0[idx];
            float4 wb = w1[idx];
            float4 va = q0[idx];
            float4 vb = q1[idx];
            a00 += wa.x * va.x + wa.y * va.y + wa.z * va.z + wa.w * va.w;
            a01 += wa.x * vb.x + wa.y * vb.y + wa.z * vb.z + wa.w * vb.w;
            a10 += wb.x * va.x + wb.y * va.y + wb.z * va.z + wb.w * va.w;
            a11 += wb.x * vb.x + wb.y * vb.y + wb.z * vb.z + wb.w * vb.w;
        }
#pragma unroll
        for (int o = 16; o; o >>= 1) {
            a00 += __shfl_xor_sync(0xffffffffu, a00, o);
            a01 += __shfl_xor_sync(0xffffffffu, a01, o);
            a10 += __shfl_xor_sync(0xffffffffu, a10, o);
            a11 += __shfl_xor_sync(0xffffffffu, a11, o);
        }
        if (lane == 0) {
            const int b0 = bt * 2, b1 = b0 + 1;
            g_mids[(size_t)b0 * KDIM + k0] = a00;
            g_mids[(size_t)b1 * KDIM + k0] = a01;
            g_mids[(size_t)b0 * KDIM + k1] = a10;
            g_mids[(size_t)b1 * KDIM + k1] = a11;
        }
    }
}

// ---------------------------------------------------------------------------
// Kernel 2: e[b,t] = exp(tanh(key[b,t,:] . mids[b,:] + bias)); accumulate
// per-batch sums. tanh in (-1,1) -> exp bounded -> no max pass needed.
// grid = 64*16 = 1024 blocks, 256 threads (8 warps). Each warp: 16 rows,
// 4 at a time -> 16 independent LDG.128 (streaming) in flight; mids held in
// REGISTERS (4 float4/lane), zero shared-memory traffic in the hot loop.
// Lane 0 writes each 4-row group as one coalesced float4.
// ---------------------------------------------------------------------------
__global__ void __launch_bounds__(256)
scores_kernel(const float* __restrict__ key,
              const float* __restrict__ bias,
              float* __restrict__ out)
{
    const int b     = blockIdx.x >> 4;   // 0..63
    const int chunk = blockIdx.x & 15;   // 0..15 (128 rows each)

    __shared__ float blockSum;
    if (threadIdx.x == 0) blockSum = 0.0f;

    const int warp = threadIdx.x >> 5;
    const int lane = threadIdx.x & 31;

    // mids for this batch, cached in registers: element span 4*(lane+32j)
    const float4* m4g = reinterpret_cast<const float4*>(g_mids + (size_t)b * KDIM);
    float4 m[4];
#pragma unroll
    for (int j = 0; j < 4; j++) m[j] = m4g[lane + 32 * j];

    const float bv = bias[0];
    const int t0 = chunk * 128 + warp * 16;

    float wsum = 0.0f;

#pragma unroll
    for (int it = 0; it < 4; it++) {
        const int ta = t0 + it * 4;
        const float4* k0 = reinterpret_cast<const float4*>(
            key + ((size_t)b * TDIM + ta + 0) * KDIM);
        const float4* k1 = reinterpret_cast<const float4*>(
            key + ((size_t)b * TDIM + ta + 1) * KDIM);
        const float4* k2 = reinterpret_cast<const float4*>(
            key + ((size_t)b * TDIM + ta + 2) * KDIM);
        const float4* k3 = reinterpret_cast<const float4*>(
            key + ((size_t)b * TDIM + ta + 3) * KDIM);

        float a0 = 0.f, a1 = 0.f, a2 = 0.f, a3 = 0.f;
#pragma unroll
        for (int j = 0; j < 4; j++) {
            const int idx = lane + 32 * j;
            float4 v0 = __ldcs(&k0[idx]);
            float4 v1 = __ldcs(&k1[idx]);
            float4 v2 = __ldcs(&k2[idx]);
            float4 v3 = __ldcs(&k3[idx]);
            const float4 mv = m[j];
            a0 += v0.x * mv.x + v0.y * mv.y + v0.z * mv.z + v0.w * mv.w;
            a1 += v1.x * mv.x + v1.y * mv.y + v1.z * mv.z + v1.w * mv.w;
            a2 += v2.x * mv.x + v2.y * mv.y + v2.z * mv.z + v2.w * mv.w;
            a3 += v3.x * mv.x + v3.y * mv.y + v3.z * mv.z + v3.w * mv.w;
        }
#pragma unroll
        for (int o = 16; o; o >>= 1) {
            a0 += __shfl_xor_sync(0xffffffffu, a0, o);
            a1 += __shfl_xor_sync(0xffffffffu, a1, o);
            a2 += __shfl_xor_sync(0xffffffffu, a2, o);
            a3 += __shfl_xor_sync(0xffffffffu, a3, o);
        }
        if (lane == 0) {
            float4 e;
            e.x = __expf(tanhf(a0 + bv));
            e.y = __expf(tanhf(a1 + bv));
            e.z = __expf(tanhf(a2 + bv));
            e.w = __expf(tanhf(a3 + bv));
            *reinterpret_cast<float4*>(out + (size_t)b * TDIM + ta) = e;
            wsum += (e.x + e.y) + (e.z + e.w);
        }
    }

    __syncthreads();  // blockSum init visible
    if (lane == 0) atomicAdd(&blockSum, wsum);
    __syncthreads();
    if (threadIdx.x == 0) atomicAdd(&g_sums[b], blockSum);
}

// ---------------------------------------------------------------------------
// Kernel 3: normalize in place. 32768 float4s, b = (float4 index) / 512.
// ---------------------------------------------------------------------------
__global__ void norm_kernel(float* __restrict__ out)
{
    const int i = blockIdx.x * blockDim.x + threadIdx.x; // 0..32767
    const int b = i >> 9;  // 512 float4 per batch row (T=2048)
    const float inv = 1.0f / g_sums[b];
    float4* o4 = reinterpret_cast<float4*>(out);
    float4 v = o4[i];
    v.x *= inv; v.y *= inv; v.z *= inv; v.w *= inv;
    o4[i] = v;
}

// ---------------------------------------------------------------------------
// Inputs (metadata order): query [64,512], key [64,2048,512], W [512,512],
// bias [1]. Output: [64,2048] float32.
// ---------------------------------------------------------------------------
extern "C" void kernel_launch(void* const* d_in, const int* in_sizes, int n_in,
                              void* d_out, int out_size)
{
    const float* query = (const float*)d_in[0];
    const float* key   = (const float*)d_in[1];
    const float* W     = (const float*)d_in[2];
    const float* bias  = (const float*)d_in[3];
    float* out = (float*)d_out;

    mids_kernel<<<256, 256>>>(query, W);
    scores_kernel<<<BATCH * 16, 256>>>(key, bias, out);
    norm_kernel<<<(BATCH * TDIM / 4) / 256, 256>>>(out);
}